// round 12
// baseline (speedup 1.0000x reference)
#include <cuda_runtime.h>
#include <cstdint>

#define NGATE 128
#define NLOG  17
#define NBLK  145
#define NTHR  128
#define HID   512
#define BB    32
#define TT    32
#define INF_  397
#define NOUT  129

#define LOGITS_ELEMS 132096
#define HC_ELEMS     16384

// smem floats: sW 8192 | sh 20480 (gate: precompute/h-stage; logits: th-stage 16384) | pad
#define SMEM_FLOATS 28840
#define SMEM_BYTES  (SMEM_FLOATS * 4)

__device__ __align__(16) float g_pre[TT * 2048 * BB];   // [t][row][b]
__device__ __align__(16) float g_h[HID * BB];           // h,  PAIR-PACKED [kp][b][2]
__device__ __align__(16) float g_th[HID * BB];          // th, PAIR-PACKED [kp][b][2]
__device__ __align__(16) unsigned long long g_best[TT][BB];  // packed argmax keys
__device__ __align__(128) unsigned g_hdone[TT];  // +NGATE per launch per slot
__device__ __align__(128) unsigned g_done[TT];   // +NBLK per launch per slot (t<TT-1)
__device__ __align__(128) unsigned g_epoch;      // +1 per launch

__device__ __forceinline__ float sigm(float x) { return 1.f / (1.f + __expf(-x)); }
__device__ __forceinline__ float tanh_p(float x) {
    float e = __expf(-2.f * fabsf(x));
    float r = (1.f - e) / (1.f + e);
    return copysignf(r, x);
}
__device__ __forceinline__ void ffma2u(unsigned long long& acc, unsigned long long w, unsigned long long h) {
    asm volatile("fma.rn.f32x2 %0, %1, %2, %0;" : "+l"(acc) : "l"(w), "l"(h));
}
__device__ __forceinline__ float2 unpack2(unsigned long long v) {
    float2 r; asm("mov.b64 {%0, %1}, %2;" : "=f"(r.x), "=f"(r.y) : "l"(v)); return r;
}
// monotone f32->u32 order embedding; key=(mkey<<32)|(255-o): max key == max
// logit, ties -> smallest o == first-max == jnp.argmax.
__device__ __forceinline__ unsigned long long pack_key(float f, int o) {
    unsigned u = __float_as_uint(f);
    u = (u & 0x80000000u) ? ~u : (u | 0x80000000u);
    return (((unsigned long long)u) << 32) | (unsigned)(255 - o);
}
__device__ __forceinline__ void rel_add(unsigned* p) {
    asm volatile("red.release.gpu.global.add.u32 [%0], 1;" :: "l"(p) : "memory");
}
__device__ __forceinline__ void acq_poll(const unsigned* p, unsigned want) {
    unsigned v;
    do {
        asm volatile("ld.acquire.gpu.global.u32 %0, [%1];" : "=r"(v) : "l"(p) : "memory");
    } while ((int)(v - want) < 0);
}

__global__ void __launch_bounds__(NTHR, 1)
decoder_kernel(const float* __restrict__ chords, const float* __restrict__ latent,
               const float* __restrict__ W_ih, const float* __restrict__ W_hh,
               const float* __restrict__ b_ih, const float* __restrict__ b_hh,
               const float* __restrict__ W_lin, const float* __restrict__ b_lin,
               float* __restrict__ out, int out_size)
{
    extern __shared__ float smem[];
    float* sW = smem;                  // 8192
    float* sh = smem + 8192;           // 20480 (gate h-stage 16384 / logits th-stage 16384)
    unsigned* sE = (unsigned*)(smem + 8192 + 20480);

    const int tid  = threadIdx.x;
    const int lane = tid & 31;
    const int wid  = tid >> 5;
    const int bid  = blockIdx.x;       // 0..127 gate, 128..144 logits

    if (tid == 0) {
        unsigned e0;
        asm volatile("ld.acquire.gpu.global.u32 %0, [%1];"
                     : "=r"(e0) : "l"(&g_epoch) : "memory");
        sE[0] = e0;
    }
    // per-launch reset of argmax keys (gate CTAs bid<32 own slot t=bid).
    // Visible to logits' red.max because they first acquire hdone[t] >= 128,
    // which includes this CTA's release (ordered after these plain stores).
    if (bid < TT && tid < BB) g_best[bid][tid] = 0ull;

    if (bid < NGATE) {
        // ======================= GATE CTA =======================
        const int j = (bid << 2) + wid;

        {   // stage W_hh rows
            float* dst = sW + wid * 2048;
            #pragma unroll
            for (int g = 0; g < 4; ++g) {
                const float* src = W_hh + (size_t)(g * HID + j) * HID;
                for (int k = (lane << 2); k < 512; k += 128)
                    *(float4*)(dst + g * 512 + k) = *(const float4*)(src + k);
            }
        }
        for (int i = tid; i < BB * 256; i += NTHR) {
            int b = i >> 8, l = i & 255;
            sh[l * 32 + b] = latent[i];
        }
        {
            float* sch = sh + 8192;
            for (int i = tid; i < BB * TT * 12; i += NTHR) {
                int b = i / 384, rem = i - b * 384;
                sch[rem * 32 + b] = chords[i];
            }
        }
        __syncthreads();
        {   // precompute g_pre
            const float* sch = sh + 8192;
            #pragma unroll
            for (int g = 0; g < 4; ++g) {
                const int row = g * HID + j;
                const float* wrow = W_ih + (size_t)row * INF_;
                float acc = __ldg(b_ih + row) + __ldg(b_hh + row);
                #pragma unroll 8
                for (int k = 0; k < 256; ++k)
                    acc = fmaf(sh[k * 32 + lane], __ldg(wrow + k), acc);
                float wc[12];
                #pragma unroll
                for (int cc = 0; cc < 12; ++cc) wc[cc] = __ldg(wrow + 385 + cc);
                for (int t = 0; t < TT; ++t) {
                    float z = acc;
                    #pragma unroll
                    for (int cc = 0; cc < 12; ++cc)
                        z = fmaf(sch[(t * 12 + cc) * 32 + lane], wc[cc], z);
                    g_pre[((size_t)(t * 2048) + row) * 32 + lane] = z;
                }
            }
        }
        __syncthreads();
        const unsigned ep0 = sE[0];
        const unsigned HT = ep0 * NGATE + NGATE;
        const unsigned DT = ep0 * NBLK + NBLK;

        const int r0 = j, r1 = HID + j, r2 = 2 * HID + j, r3 = 3 * HID + j;
        const float* w0 = sW + wid * 2048;
        const float* w1 = w0 + 512;
        const float* w2 = w0 + 1024;
        const float* w3 = w0 + 1536;
        float creg = 0.f;

        for (int t = 0; t < TT; ++t) {
            const float* prebase = g_pre + (size_t)(t * 2048) * 32;
            float zi = prebase[r0 * 32 + lane];
            float zf = prebase[r1 * 32 + lane];
            float zg = prebase[r2 * 32 + lane];
            float zo = prebase[r3 * 32 + lane];

            if (t > 0) {
                // dot first (sh holds h(t-1), staged at previous tail)
                const unsigned long long* sh64 = (const unsigned long long*)sh;
                unsigned long long A0 = 0, A1 = 0, A2 = 0, A3 = 0;
                #pragma unroll 4
                for (int k = 0; k < 512; k += 4) {
                    const int kp = k >> 1;
                    unsigned long long h01 = sh64[kp * 32 + lane];
                    unsigned long long h23 = sh64[(kp + 1) * 32 + lane];
                    ulonglong2 Wa = *(const ulonglong2*)(w0 + k);
                    ulonglong2 Wb = *(const ulonglong2*)(w1 + k);
                    ulonglong2 Wc = *(const ulonglong2*)(w2 + k);
                    ulonglong2 Wd = *(const ulonglong2*)(w3 + k);
                    ffma2u(A0, Wa.x, h01); ffma2u(A1, Wb.x, h01);
                    ffma2u(A2, Wc.x, h01); ffma2u(A3, Wd.x, h01);
                    ffma2u(A0, Wa.y, h23); ffma2u(A1, Wb.y, h23);
                    ffma2u(A2, Wc.y, h23); ffma2u(A3, Wd.y, h23);
                }
                // pidx(t-1): expected already published (logits overlapped the dot)
                if (tid == 0) acq_poll(&g_done[t - 1], DT);
                __syncthreads();
                unsigned long long key;
                asm volatile("ld.global.cg.u64 %0, [%1];"
                             : "=l"(key) : "l"(&g_best[t - 1][lane]) : "memory");
                const int pidx = 255 - (int)(unsigned)(key & 0xffu);

                zi += __ldg(W_ih + (size_t)r0 * INF_ + 256 + pidx);
                zf += __ldg(W_ih + (size_t)r1 * INF_ + 256 + pidx);
                zg += __ldg(W_ih + (size_t)r2 * INF_ + 256 + pidx);
                zo += __ldg(W_ih + (size_t)r3 * INF_ + 256 + pidx);
                float2 u0 = unpack2(A0), u1 = unpack2(A1);
                float2 u2 = unpack2(A2), u3 = unpack2(A3);
                zi += u0.x + u0.y; zf += u1.x + u1.y;
                zg += u2.x + u2.y; zo += u3.x + u3.y;
            }

            const float gi = sigm(zi), gf = sigm(zf), gg = tanh_p(zg), go = sigm(zo);
            creg = gf * creg + gi * gg;
            const float hv = go * tanh_p(creg);
            const float th = tanh_p(hv);
            const int pp = (j >> 1) * 64 + lane * 2 + (j & 1);   // pair-packed slot
            g_h[pp]  = hv;
            g_th[pp] = th;
            if (t == TT - 1 && out_size >= LOGITS_ELEMS + 2 * HC_ELEMS) {
                out[LOGITS_ELEMS + lane * HID + j]            = hv;
                out[LOGITS_ELEMS + HC_ELEMS + lane * HID + j] = creg;
            }
            __syncthreads();
            if (tid == 0) { __threadfence(); rel_add(&g_hdone[t]); }

            if (t < TT - 1) {
                if (tid == 0) acq_poll(&g_hdone[t], HT);
                __syncthreads();
                // stage h(t) for next step's dot
                const float4* src4 = (const float4*)g_h;
                float4* dst4 = (float4*)sh;
                #pragma unroll 4
                for (int i = tid; i < HID * BB / 4; i += NTHR) dst4[i] = __ldcg(src4 + i);
                __syncthreads();   // STS drained => my h(t) reads retired
                if (tid == 0) { __threadfence(); rel_add(&g_done[t]); }
            }
        }
        if (bid == 0 && tid == 0) rel_add(&g_epoch);   // everyone read base by step 1
        return;
    }

    // ======================= LOGITS CTA =======================
    __syncthreads();   // sE visible
    const unsigned ep0 = sE[0];
    const unsigned HT = ep0 * NGATE + NGATE;
    const int L  = bid - NGATE;            // 0..16
    const int o0 = L * 8 + wid * 2;        // even column
    const int o1 = o0 + 1;                 // odd column
    const bool v0 = (o0 < NOUT), v1 = (o1 < NOUT);

    for (int t = 0; t < TT; ++t) {
        if (tid == 0) acq_poll(&g_hdone[t], HT);
        __syncthreads();   // also: all warps done reading sh from previous step

        // stage th(t) (pair-packed raw copy) into smem
        {
            const float4* src4 = (const float4*)g_th;
            float4* dst4 = (float4*)sh;
            #pragma unroll 4
            for (int i = tid; i < HID * BB / 4; i += NTHR) dst4[i] = __ldcg(src4 + i);
        }
        __syncthreads();

        if (v0) {
            const unsigned long long* sth = (const unsigned long long*)sh;
            const float* wr0 = W_lin + (size_t)o0 * HID;
            const float* wr1 = W_lin + (size_t)o1 * HID;
            unsigned long long A00 = 0, A01 = 0, A10 = 0, A11 = 0;
            #pragma unroll 4
            for (int kp = 0; kp < 256; kp += 2) {
                unsigned long long t01 = sth[kp * 32 + lane];
                unsigned long long t23 = sth[(kp + 1) * 32 + lane];
                ulonglong2 W0 = __ldg((const ulonglong2*)(wr0 + kp * 2));
                ffma2u(A00, W0.x, t01); ffma2u(A01, W0.y, t23);
                if (v1) {
                    ulonglong2 W1 = __ldg((const ulonglong2*)(wr1 + kp * 2));
                    ffma2u(A10, W1.x, t01); ffma2u(A11, W1.y, t23);
                }
            }
            float2 a = unpack2(A00), b2 = unpack2(A01);
            float tot0 = a.x + a.y + b2.x + b2.y + __ldg(b_lin + o0);
            out[lane * (TT * NOUT) + t * NOUT + o0] = tot0;
            unsigned long long key = pack_key(tot0, o0);
            if (v1) {
                float2 c = unpack2(A10), d = unpack2(A11);
                float tot1 = c.x + c.y + d.x + d.y + __ldg(b_lin + o1);
                out[lane * (TT * NOUT) + t * NOUT + o1] = tot1;
                unsigned long long k1 = pack_key(tot1, o1);
                if (k1 > key) key = k1;
            }
            if (t < TT - 1) {
                asm volatile("red.relaxed.gpu.global.max.u64 [%0], %1;"
                             :: "l"(&g_best[t][lane]), "l"(key) : "memory");
            }
        }
        __syncthreads();   // all warps' red.max issued before the release below
        if (t < TT - 1 && tid == 0) { __threadfence(); rel_add(&g_done[t]); }
    }
}

extern "C" void kernel_launch(void* const* d_in, const int* in_sizes, int n_in,
                              void* d_out, int out_size) {
    const int want[8] = {12288, 8192, 813056, 1048576, 2048, 2048, 66048, 129};
    const float* p[8] = {nullptr, nullptr, nullptr, nullptr, nullptr, nullptr, nullptr, nullptr};
    bool used[64] = {false};
    for (int w = 0; w < 8; ++w) {
        for (int i = 0; i < n_in && i < 64; ++i) {
            if (!used[i] && in_sizes[i] == want[w]) {
                p[w] = (const float*)d_in[i];
                used[i] = true;
                break;
            }
        }
    }
    cudaFuncSetAttribute(decoder_kernel, cudaFuncAttributeMaxDynamicSharedMemorySize, SMEM_BYTES);
    decoder_kernel<<<NBLK, NTHR, SMEM_BYTES>>>(p[0], p[1], p[2], p[3], p[4], p[5], p[6], p[7],
                                               (float*)d_out, out_size);
}

// round 13
// speedup vs baseline: 1.5128x; 1.5128x over previous
#include <cuda_runtime.h>
#include <cstdint>

#define NGATE 128
#define NBLK  129
#define NTHR  128
#define HID   512
#define BB    32
#define TT    32
#define INF_  397
#define NOUT  129
#define NSH   16      // counter shards (one 128B line each)
#define BSH   4       // argmax-key shards

#define LOGITS_ELEMS 132096
#define HC_ELEMS     16384

// smem floats: sW 8192 | sh 20480 | sred 128 | pad 32 | sE
#define SMEM_FLOATS 28840
#define SMEM_BYTES  (SMEM_FLOATS * 4)

__device__ __align__(16) float g_pre[TT * 2048 * BB];   // [t][row][b]
__device__ __align__(16) float g_h[HID * BB];           // h, PAIR-PACKED [kp][b][2]
__device__ __align__(16) float g_th[HID * BB];          // tanh(h), [k][b]
__device__ __align__(16) unsigned long long g_best2[TT][BSH][BB];  // sharded argmax keys
__device__ __align__(128) unsigned g_hdone2[TT * NSH * 32];  // shard line stride 128B; +8/launch
__device__ __align__(128) unsigned g_done2[TT * NSH * 32];   // +8 (+1 on shard 0)/launch
__device__ __align__(128) unsigned g_epoch;                  // +1 per launch

__device__ __forceinline__ float sigm(float x) { return 1.f / (1.f + __expf(-x)); }
__device__ __forceinline__ float tanh_p(float x) {
    float e = __expf(-2.f * fabsf(x));
    float r = (1.f - e) / (1.f + e);
    return copysignf(r, x);
}
__device__ __forceinline__ void ffma2u(unsigned long long& acc, unsigned long long w, unsigned long long h) {
    asm volatile("fma.rn.f32x2 %0, %1, %2, %0;" : "+l"(acc) : "l"(w), "l"(h));
}
__device__ __forceinline__ float2 unpack2(unsigned long long v) {
    float2 r; asm("mov.b64 {%0, %1}, %2;" : "=f"(r.x), "=f"(r.y) : "l"(v)); return r;
}
// monotone f32->u32 order embedding; key=(mkey<<32)|(255-o): max key == max
// logit, ties -> smallest o == first-max == jnp.argmax. Associative -> shardable.
__device__ __forceinline__ unsigned long long pack_key(float f, int o) {
    unsigned u = __float_as_uint(f);
    u = (u & 0x80000000u) ? ~u : (u | 0x80000000u);
    return (((unsigned long long)u) << 32) | (unsigned)(255 - o);
}
__device__ __forceinline__ void rel_add(unsigned* p) {
    asm volatile("red.release.gpu.global.add.u32 [%0], 1;" :: "l"(p) : "memory");
}
__device__ __forceinline__ void acq_poll(const unsigned* p, unsigned want) {
    unsigned v;
    do {
        asm volatile("ld.acquire.gpu.global.u32 %0, [%1];" : "=r"(v) : "l"(p) : "memory");
    } while ((int)(v - want) < 0);
}
__device__ __forceinline__ unsigned long long ldcg_u64(const unsigned long long* p) {
    unsigned long long v;
    asm volatile("ld.global.cg.u64 %0, [%1];" : "=l"(v) : "l"(p) : "memory");
    return v;
}

__global__ void __launch_bounds__(NTHR, 1)
decoder_kernel(const float* __restrict__ chords, const float* __restrict__ latent,
               const float* __restrict__ W_ih, const float* __restrict__ W_hh,
               const float* __restrict__ b_ih, const float* __restrict__ b_hh,
               const float* __restrict__ W_lin, const float* __restrict__ b_lin,
               float* __restrict__ out, int out_size)
{
    extern __shared__ float smem[];
    float* sW   = smem;                  // 8192
    float* sh   = smem + 8192;           // 20480
    float* sred = smem + 8192 + 20480;   // 128
    unsigned* sE = (unsigned*)(sred + 128 + 32);

    const int tid  = threadIdx.x;
    const int lane = tid & 31;
    const int wid  = tid >> 5;
    const int bid  = blockIdx.x;         // 0..128; bid==128 is logits-only
    const int j    = (bid << 2) + wid;   // hidden unit (valid for bid < 128)

    if (tid == 0) {
        unsigned e0;
        asm volatile("ld.acquire.gpu.global.u32 %0, [%1];"
                     : "=r"(e0) : "l"(&g_epoch) : "memory");
        sE[0] = e0;
    }
    // per-launch reset of sharded argmax keys (CTA bid<32 owns slot t=bid).
    // Visible to all red.max writers because they first acquire hdone[t] full,
    // which includes this CTA's step-t release (ordered after these stores).
    if (bid < TT) ((unsigned long long*)g_best2[bid])[tid] = 0ull;   // 128 = BSH*BB

    if (bid < NGATE) {
        // ---- Stage W_hh rows into smem ----
        {
            float* dst = sW + wid * 2048;
            #pragma unroll
            for (int g = 0; g < 4; ++g) {
                const float* src = W_hh + (size_t)(g * HID + j) * HID;
                for (int k = (lane << 2); k < 512; k += 128)
                    *(float4*)(dst + g * 512 + k) = *(const float4*)(src + k);
            }
        }
        for (int i = tid; i < BB * 256; i += NTHR) {
            int b = i >> 8, l = i & 255;
            sh[l * 32 + b] = latent[i];
        }
        {
            float* sch = sh + 8192;
            for (int i = tid; i < BB * TT * 12; i += NTHR) {
                int b = i / 384, rem = i - b * 384;
                sch[rem * 32 + b] = chords[i];
            }
        }
        __syncthreads();
        // ---- Precompute g_pre[t][row][b] ----
        {
            const float* sch = sh + 8192;
            #pragma unroll
            for (int g = 0; g < 4; ++g) {
                const int row = g * HID + j;
                const float* wrow = W_ih + (size_t)row * INF_;
                float acc = __ldg(b_ih + row) + __ldg(b_hh + row);
                #pragma unroll 8
                for (int k = 0; k < 256; ++k)
                    acc = fmaf(sh[k * 32 + lane], __ldg(wrow + k), acc);
                float wc[12];
                #pragma unroll
                for (int cc = 0; cc < 12; ++cc) wc[cc] = __ldg(wrow + 385 + cc);
                for (int t = 0; t < TT; ++t) {
                    float z = acc;
                    #pragma unroll
                    for (int cc = 0; cc < 12; ++cc)
                        z = fmaf(sch[(t * 12 + cc) * 32 + lane], wc[cc], z);
                    g_pre[((size_t)(t * 2048) + row) * 32 + lane] = z;
                }
            }
        }
        __syncthreads();
    } else {
        __syncthreads();
    }
    const unsigned ep0 = sE[0];
    const unsigned HT = (ep0 + 1) * (NGATE / NSH);               // hdone per-shard target
    const unsigned DT = (ep0 + 1) * (NBLK / NSH);                // done shards 1..15
    const unsigned DT0 = (ep0 + 1) * (NBLK / NSH + 1);           // done shard 0 (9 bids)

    const int r0 = j, r1 = HID + j, r2 = 2 * HID + j, r3 = 3 * HID + j;
    const float* w0 = sW + wid * 2048;
    const float* w1 = w0 + 512;
    const float* w2 = w0 + 1024;
    const float* w3 = w0 + 1536;
    const int csh = bid & (NSH - 1);     // this CTA's counter shard
    const int ksh = bid & (BSH - 1);     // this CTA's key shard

    float creg = 0.f;

    for (int t = 0; t < TT; ++t) {
        if (bid < NGATE) {
            __syncthreads();   // sh holds h(t-1); staging STS drained last iteration

            const float* prebase = g_pre + (size_t)(t * 2048) * 32;
            float zi = prebase[r0 * 32 + lane];
            float zf = prebase[r1 * 32 + lane];
            float zg = prebase[r2 * 32 + lane];
            float zo = prebase[r3 * 32 + lane];

            if (t > 0) {
                // ---- recurrent dot FIRST (doesn't need pidx) ----
                const unsigned long long* sh64 = (const unsigned long long*)sh;
                unsigned long long A0 = 0, A1 = 0, A2 = 0, A3 = 0;
                #pragma unroll 4
                for (int k = 0; k < 512; k += 4) {
                    const int kp = k >> 1;
                    unsigned long long h01 = sh64[kp * 32 + lane];
                    unsigned long long h23 = sh64[(kp + 1) * 32 + lane];
                    ulonglong2 Wa = *(const ulonglong2*)(w0 + k);
                    ulonglong2 Wb = *(const ulonglong2*)(w1 + k);
                    ulonglong2 Wc = *(const ulonglong2*)(w2 + k);
                    ulonglong2 Wd = *(const ulonglong2*)(w3 + k);
                    ffma2u(A0, Wa.x, h01); ffma2u(A1, Wb.x, h01);
                    ffma2u(A2, Wc.x, h01); ffma2u(A3, Wd.x, h01);
                    ffma2u(A0, Wa.y, h23); ffma2u(A1, Wb.y, h23);
                    ffma2u(A2, Wc.y, h23); ffma2u(A3, Wd.y, h23);
                }

                // ---- wait for argmax(t-1): poll all 16 done shards in parallel.
                //      Also certifies all CTAs finished reading h(t-1)/th(t-1).
                if (tid < NSH)
                    acq_poll(&g_done2[((t - 1) * NSH + tid) * 32], tid == 0 ? DT0 : DT);
                __syncthreads();
                unsigned long long key = ldcg_u64(&g_best2[t - 1][0][lane]);
                #pragma unroll
                for (int s = 1; s < BSH; ++s) {
                    unsigned long long k2 = ldcg_u64(&g_best2[t - 1][s][lane]);
                    if (k2 > key) key = k2;
                }
                const int pidx = 255 - (int)(unsigned)(key & 0xffu);

                zi += __ldg(W_ih + (size_t)r0 * INF_ + 256 + pidx);
                zf += __ldg(W_ih + (size_t)r1 * INF_ + 256 + pidx);
                zg += __ldg(W_ih + (size_t)r2 * INF_ + 256 + pidx);
                zo += __ldg(W_ih + (size_t)r3 * INF_ + 256 + pidx);
                float2 u0 = unpack2(A0), u1 = unpack2(A1);
                float2 u2 = unpack2(A2), u3 = unpack2(A3);
                zi += u0.x + u0.y; zf += u1.x + u1.y;
                zg += u2.x + u2.y; zo += u3.x + u3.y;
            }

            const float gi = sigm(zi), gf = sigm(zf), gg = tanh_p(zg), go = sigm(zo);
            creg = gf * creg + gi * gg;
            const float hv = go * tanh_p(creg);
            const float th = tanh_p(hv);
            g_h[(j >> 1) * 64 + lane * 2 + (j & 1)] = hv;   // pair-packed
            g_th[j * 32 + lane] = th;                       // [k][b]
            if (t == TT - 1 && out_size >= LOGITS_ELEMS + 2 * HC_ELEMS) {
                out[LOGITS_ELEMS + lane * HID + j]            = hv;
                out[LOGITS_ELEMS + HC_ELEMS + lane * HID + j] = creg;
            }
            __syncthreads();            // all 4 warps' h/th stores done
            if (tid == 0) {
                __threadfence();
                rel_add(&g_hdone2[(t * NSH + csh) * 32]);   // publish h(t)/th(t)
            }
        }

        // ---- wait until ALL gate CTAs published h(t)/th(t): 16 parallel shards ----
        if (tid < NSH) acq_poll(&g_hdone2[(t * NSH + tid) * 32], HT);
        __syncthreads();

        // ---- stage h(t) for next step's dot (gate CTAs; overlaps logits) ----
        if (bid < NGATE && t < TT - 1) {
            const float4* src4 = (const float4*)g_h;
            float4* dst4 = (float4*)sh;
            #pragma unroll 4
            for (int i = tid; i < HID * BB / 4; i += NTHR) dst4[i] = __ldcg(src4 + i);
        }

        // ---- logits column o = bid (all CTAs; arithmetic identical to R10/R11) ----
        {
            const int o = bid;
            const float* wl  = W_lin + (size_t)o * HID + wid * 128;
            const float* thp = g_th + (wid * 128) * 32;
            float c0 = 0.f, c1 = 0.f, c2 = 0.f, c3 = 0.f;
            #pragma unroll
            for (int k = 0; k < 128; k += 4) {
                c0 = fmaf(__ldcg(thp + (k + 0) * 32 + lane), __ldg(wl + k + 0), c0);
                c1 = fmaf(__ldcg(thp + (k + 1) * 32 + lane), __ldg(wl + k + 1), c1);
                c2 = fmaf(__ldcg(thp + (k + 2) * 32 + lane), __ldg(wl + k + 2), c2);
                c3 = fmaf(__ldcg(thp + (k + 3) * 32 + lane), __ldg(wl + k + 3), c3);
            }
            sred[wid * 32 + lane] = (c0 + c1) + (c2 + c3);
            __syncthreads();   // drains staging STS (h(t) reads retired) + sred
            if (wid == 0) {
                float tot = sred[lane] + sred[32 + lane] + sred[64 + lane]
                          + sred[96 + lane] + __ldg(b_lin + o);
                out[lane * (TT * NOUT) + t * NOUT + o] = tot;
                if (t < TT - 1) {
                    unsigned long long key = pack_key(tot, o);
                    asm volatile("red.relaxed.gpu.global.max.u64 [%0], %1;"
                                 :: "l"(&g_best2[t][ksh][lane]), "l"(key) : "memory");
                }
            }
            __syncthreads();
            if (t < TT - 1 && tid == 0) {
                __threadfence();
                rel_add(&g_done2[(t * NSH + csh) * 32]);   // column + gen-t reads done
            }
        }
    }

    // exactly one epoch bump per launch; after every CTA has read its base
    // (CTA0's t=31 done-poll of slot 30 includes every CTA's release).
    if (bid == 0 && tid == 0) rel_add(&g_epoch);
}

extern "C" void kernel_launch(void* const* d_in, const int* in_sizes, int n_in,
                              void* d_out, int out_size) {
    const int want[8] = {12288, 8192, 813056, 1048576, 2048, 2048, 66048, 129};
    const float* p[8] = {nullptr, nullptr, nullptr, nullptr, nullptr, nullptr, nullptr, nullptr};
    bool used[64] = {false};
    for (int w = 0; w < 8; ++w) {
        for (int i = 0; i < n_in && i < 64; ++i) {
            if (!used[i] && in_sizes[i] == want[w]) {
                p[w] = (const float*)d_in[i];
                used[i] = true;
                break;
            }
        }
    }
    cudaFuncSetAttribute(decoder_kernel, cudaFuncAttributeMaxDynamicSharedMemorySize, SMEM_BYTES);
    decoder_kernel<<<NBLK, NTHR, SMEM_BYTES>>>(p[0], p[1], p[2], p[3], p[4], p[5], p[6], p[7],
                                               (float*)d_out, out_size);
}

// round 15
// speedup vs baseline: 1.5176x; 1.0032x over previous
#include <cuda_runtime.h>
#include <cstdint>

#define NGATE 128
#define NBLK  129
#define NTHR  128
#define HID   512
#define BB    32
#define TT    32
#define INF_  397
#define NOUT  129
#define NSH   16      // counter shards (one 128B line each)
#define BSH   4       // argmax-key shards

#define LOGITS_ELEMS 132096
#define HC_ELEMS     16384

// smem floats: sW 8192 | sh 20480 | sred 128 | pad 32 | sE
#define SMEM_FLOATS 28840
#define SMEM_BYTES  (SMEM_FLOATS * 4)

__device__ __align__(16) float g_pre[TT * 2048 * BB];   // [t][row][b]
__device__ __align__(16) float g_h[HID * BB];           // h, PAIR-PACKED [kp][b][2]
__device__ __align__(16) float g_th[HID * BB];          // tanh(h), [k][b]
__device__ __align__(16) unsigned long long g_best2[TT][BSH][BB];  // sharded argmax keys
__device__ __align__(128) unsigned g_hdone2[TT * NSH * 32];  // shard line stride 128B; +8/launch
__device__ __align__(128) unsigned g_done2[TT * NSH * 32];   // +8 (+1 on shard 0)/launch
__device__ __align__(128) unsigned g_epoch;                  // +1 per launch

__device__ __forceinline__ float sigm(float x) { return 1.f / (1.f + __expf(-x)); }
__device__ __forceinline__ float tanh_p(float x) {
    float e = __expf(-2.f * fabsf(x));
    float r = (1.f - e) / (1.f + e);
    return copysignf(r, x);
}
__device__ __forceinline__ void ffma2u(unsigned long long& acc, unsigned long long w, unsigned long long h) {
    asm volatile("fma.rn.f32x2 %0, %1, %2, %0;" : "+l"(acc) : "l"(w), "l"(h));
}
__device__ __forceinline__ float2 unpack2(unsigned long long v) {
    float2 r; asm("mov.b64 {%0, %1}, %2;" : "=f"(r.x), "=f"(r.y) : "l"(v)); return r;
}
// monotone f32->u32 order embedding; key=(mkey<<32)|(255-o): max key == max
// logit, ties -> smallest o == first-max == jnp.argmax. Associative -> shardable.
__device__ __forceinline__ unsigned long long pack_key(float f, int o) {
    unsigned u = __float_as_uint(f);
    u = (u & 0x80000000u) ? ~u : (u | 0x80000000u);
    return (((unsigned long long)u) << 32) | (unsigned)(255 - o);
}
__device__ __forceinline__ void rel_add(unsigned* p) {
    asm volatile("red.release.gpu.global.add.u32 [%0], 1;" :: "l"(p) : "memory");
}
__device__ __forceinline__ void acq_poll(const unsigned* p, unsigned want) {
    unsigned v;
    do {
        asm volatile("ld.acquire.gpu.global.u32 %0, [%1];" : "=r"(v) : "l"(p) : "memory");
    } while ((int)(v - want) < 0);
}
__device__ __forceinline__ unsigned long long ldcg_u64(const unsigned long long* p) {
    unsigned long long v;
    asm volatile("ld.global.cg.u64 %0, [%1];" : "=l"(v) : "l"(p) : "memory");
    return v;
}

__global__ void __launch_bounds__(NTHR, 1)
decoder_kernel(const float* __restrict__ chords, const float* __restrict__ latent,
               const float* __restrict__ W_ih, const float* __restrict__ W_hh,
               const float* __restrict__ b_ih, const float* __restrict__ b_hh,
               const float* __restrict__ W_lin, const float* __restrict__ b_lin,
               float* __restrict__ out, int out_size)
{
    extern __shared__ float smem[];
    float* sW   = smem;                  // 8192
    float* sh   = smem + 8192;           // 20480
    float* sred = smem + 8192 + 20480;   // 128
    unsigned* sE = (unsigned*)(sred + 128 + 32);

    const int tid  = threadIdx.x;
    const int lane = tid & 31;
    const int wid  = tid >> 5;
    const int bid  = blockIdx.x;         // 0..128; bid==128 is logits-only
    const int j    = (bid << 2) + wid;   // hidden unit (valid for bid < 128)

    if (tid == 0) {
        unsigned e0;
        asm volatile("ld.acquire.gpu.global.u32 %0, [%1];"
                     : "=r"(e0) : "l"(&g_epoch) : "memory");
        sE[0] = e0;
    }
    // per-launch reset of sharded argmax keys (CTA bid<32 owns slot t=bid).
    // Visible to all red.max writers because they first acquire hdone[t] full,
    // which includes this CTA's step-t release (ordered after these stores).
    if (bid < TT) ((unsigned long long*)g_best2[bid])[tid] = 0ull;   // 128 = BSH*BB

    if (bid < NGATE) {
        // ---- Stage W_hh rows into smem ----
        {
            float* dst = sW + wid * 2048;
            #pragma unroll
            for (int g = 0; g < 4; ++g) {
                const float* src = W_hh + (size_t)(g * HID + j) * HID;
                for (int k = (lane << 2); k < 512; k += 128)
                    *(float4*)(dst + g * 512 + k) = *(const float4*)(src + k);
            }
        }
        for (int i = tid; i < BB * 256; i += NTHR) {
            int b = i >> 8, l = i & 255;
            sh[l * 32 + b] = latent[i];
        }
        {
            float* sch = sh + 8192;
            for (int i = tid; i < BB * TT * 12; i += NTHR) {
                int b = i / 384, rem = i - b * 384;
                sch[rem * 32 + b] = chords[i];
            }
        }
        __syncthreads();
        // ---- Precompute g_pre[t][row][b] ----
        {
            const float* sch = sh + 8192;
            #pragma unroll
            for (int g = 0; g < 4; ++g) {
                const int row = g * HID + j;
                const float* wrow = W_ih + (size_t)row * INF_;
                float acc = __ldg(b_ih + row) + __ldg(b_hh + row);
                #pragma unroll 8
                for (int k = 0; k < 256; ++k)
                    acc = fmaf(sh[k * 32 + lane], __ldg(wrow + k), acc);
                float wc[12];
                #pragma unroll
                for (int cc = 0; cc < 12; ++cc) wc[cc] = __ldg(wrow + 385 + cc);
                for (int t = 0; t < TT; ++t) {
                    float z = acc;
                    #pragma unroll
                    for (int cc = 0; cc < 12; ++cc)
                        z = fmaf(sch[(t * 12 + cc) * 32 + lane], wc[cc], z);
                    g_pre[((size_t)(t * 2048) + row) * 32 + lane] = z;
                }
            }
        }
        __syncthreads();
    } else {
        __syncthreads();
    }
    const unsigned ep0 = sE[0];
    const unsigned HT = (ep0 + 1) * (NGATE / NSH);               // hdone per-shard target
    const unsigned DT = (ep0 + 1) * (NBLK / NSH);                // done shards 1..15
    const unsigned DT0 = (ep0 + 1) * (NBLK / NSH + 1);           // done shard 0 (9 bids)

    const int r0 = j, r1 = HID + j, r2 = 2 * HID + j, r3 = 3 * HID + j;
    const float* w0 = sW + wid * 2048;
    const float* w1 = w0 + 512;
    const float* w2 = w0 + 1024;
    const float* w3 = w0 + 1536;
    const int csh = bid & (NSH - 1);     // this CTA's counter shard
    const int ksh = bid & (BSH - 1);     // this CTA's key shard

    float creg = 0.f;

    for (int t = 0; t < TT; ++t) {
        if (bid < NGATE) {
            __syncthreads();   // sh holds h(t-1); staging STS drained last iteration

            const float* prebase = g_pre + (size_t)(t * 2048) * 32;
            float zi = prebase[r0 * 32 + lane];
            float zf = prebase[r1 * 32 + lane];
            float zg = prebase[r2 * 32 + lane];
            float zo = prebase[r3 * 32 + lane];

            if (t > 0) {
                // ---- recurrent dot FIRST (doesn't need pidx) ----
                const unsigned long long* sh64 = (const unsigned long long*)sh;
                unsigned long long A0 = 0, A1 = 0, A2 = 0, A3 = 0;
                #pragma unroll 4
                for (int k = 0; k < 512; k += 4) {
                    const int kp = k >> 1;
                    unsigned long long h01 = sh64[kp * 32 + lane];
                    unsigned long long h23 = sh64[(kp + 1) * 32 + lane];
                    ulonglong2 Wa = *(const ulonglong2*)(w0 + k);
                    ulonglong2 Wb = *(const ulonglong2*)(w1 + k);
                    ulonglong2 Wc = *(const ulonglong2*)(w2 + k);
                    ulonglong2 Wd = *(const ulonglong2*)(w3 + k);
                    ffma2u(A0, Wa.x, h01); ffma2u(A1, Wb.x, h01);
                    ffma2u(A2, Wc.x, h01); ffma2u(A3, Wd.x, h01);
                    ffma2u(A0, Wa.y, h23); ffma2u(A1, Wb.y, h23);
                    ffma2u(A2, Wc.y, h23); ffma2u(A3, Wd.y, h23);
                }

                // ---- wait for argmax(t-1): poll all 16 done shards in parallel.
                //      Also certifies all CTAs finished reading h(t-1)/th(t-1).
                if (tid < NSH)
                    acq_poll(&g_done2[((t - 1) * NSH + tid) * 32], tid == 0 ? DT0 : DT);
                __syncthreads();
                unsigned long long key = ldcg_u64(&g_best2[t - 1][0][lane]);
                #pragma unroll
                for (int s = 1; s < BSH; ++s) {
                    unsigned long long k2 = ldcg_u64(&g_best2[t - 1][s][lane]);
                    if (k2 > key) key = k2;
                }
                const int pidx = 255 - (int)(unsigned)(key & 0xffu);

                zi += __ldg(W_ih + (size_t)r0 * INF_ + 256 + pidx);
                zf += __ldg(W_ih + (size_t)r1 * INF_ + 256 + pidx);
                zg += __ldg(W_ih + (size_t)r2 * INF_ + 256 + pidx);
                zo += __ldg(W_ih + (size_t)r3 * INF_ + 256 + pidx);
                float2 u0 = unpack2(A0), u1 = unpack2(A1);
                float2 u2 = unpack2(A2), u3 = unpack2(A3);
                zi += u0.x + u0.y; zf += u1.x + u1.y;
                zg += u2.x + u2.y; zo += u3.x + u3.y;
            }

            const float gi = sigm(zi), gf = sigm(zf), gg = tanh_p(zg), go = sigm(zo);
            creg = gf * creg + gi * gg;
            const float hv = go * tanh_p(creg);
            const float th = tanh_p(hv);
            g_h[(j >> 1) * 64 + lane * 2 + (j & 1)] = hv;   // pair-packed
            g_th[j * 32 + lane] = th;                       // [k][b]
            if (t == TT - 1 && out_size >= LOGITS_ELEMS + 2 * HC_ELEMS) {
                out[LOGITS_ELEMS + lane * HID + j]            = hv;
                out[LOGITS_ELEMS + HC_ELEMS + lane * HID + j] = creg;
            }
            __syncthreads();            // all 4 warps' h/th stores done
            if (tid == 0) {
                __threadfence();
                rel_add(&g_hdone2[(t * NSH + csh) * 32]);   // publish h(t)/th(t)
            }
        }

        // ---- wait until ALL gate CTAs published h(t)/th(t): 16 parallel shards ----
        if (tid < NSH) acq_poll(&g_hdone2[(t * NSH + tid) * 32], HT);
        __syncthreads();

        // ---- stage h(t) for next step's dot (gate CTAs; overlaps logits) ----
        if (bid < NGATE && t < TT - 1) {
            const float4* src4 = (const float4*)g_h;
            float4* dst4 = (float4*)sh;
            #pragma unroll 4
            for (int i = tid; i < HID * BB / 4; i += NTHR) dst4[i] = __ldcg(src4 + i);
        }

        // ---- logits column o = bid (all CTAs; arithmetic identical to R10/R11) ----
        {
            const int o = bid;
            const float* wl  = W_lin + (size_t)o * HID + wid * 128;
            const float* thp = g_th + (wid * 128) * 32;
            float c0 = 0.f, c1 = 0.f, c2 = 0.f, c3 = 0.f;
            #pragma unroll
            for (int k = 0; k < 128; k += 4) {
                c0 = fmaf(__ldcg(thp + (k + 0) * 32 + lane), __ldg(wl + k + 0), c0);
                c1 = fmaf(__ldcg(thp + (k + 1) * 32 + lane), __ldg(wl + k + 1), c1);
                c2 = fmaf(__ldcg(thp + (k + 2) * 32 + lane), __ldg(wl + k + 2), c2);
                c3 = fmaf(__ldcg(thp + (k + 3) * 32 + lane), __ldg(wl + k + 3), c3);
            }
            sred[wid * 32 + lane] = (c0 + c1) + (c2 + c3);
            __syncthreads();   // drains staging STS (h(t) reads retired) + sred
            if (wid == 0) {
                float tot = sred[lane] + sred[32 + lane] + sred[64 + lane]
                          + sred[96 + lane] + __ldg(b_lin + o);
                out[lane * (TT * NOUT) + t * NOUT + o] = tot;
                if (t < TT - 1) {
                    unsigned long long key = pack_key(tot, o);
                    asm volatile("red.relaxed.gpu.global.max.u64 [%0], %1;"
                                 :: "l"(&g_best2[t][ksh][lane]), "l"(key) : "memory");
                }
            }
            __syncthreads();
            if (t < TT - 1 && tid == 0) {
                __threadfence();
                rel_add(&g_done2[(t * NSH + csh) * 32]);   // column + gen-t reads done
            }
        }
    }

    // exactly one epoch bump per launch; after every CTA has read its base
    // (CTA0's t=31 done-poll of slot 30 includes every CTA's release).
    if (bid == 0 && tid == 0) rel_add(&g_epoch);
}

extern "C" void kernel_launch(void* const* d_in, const int* in_sizes, int n_in,
                              void* d_out, int out_size) {
    const int want[8] = {12288, 8192, 813056, 1048576, 2048, 2048, 66048, 129};
    const float* p[8] = {nullptr, nullptr, nullptr, nullptr, nullptr, nullptr, nullptr, nullptr};
    bool used[64] = {false};
    for (int w = 0; w < 8; ++w) {
        for (int i = 0; i < n_in && i < 64; ++i) {
            if (!used[i] && in_sizes[i] == want[w]) {
                p[w] = (const float*)d_in[i];
                used[i] = true;
                break;
            }
        }
    }
    cudaFuncSetAttribute(decoder_kernel, cudaFuncAttributeMaxDynamicSharedMemorySize, SMEM_BYTES);
    decoder_kernel<<<NBLK, NTHR, SMEM_BYTES>>>(p[0], p[1], p[2], p[3], p[4], p[5], p[6], p[7],
                                               (float*)d_out, out_size);
}

// round 16
// speedup vs baseline: 1.5823x; 1.0427x over previous
#include <cuda_runtime.h>
#include <cstdint>

#define NGATE 128
#define NBLK  129
#define NTHR  128
#define HID   512
#define BB    32
#define TT    32
#define INF_  397
#define NOUT  129
#define NSH   16      // counter shards (one 128B line each)
#define BSH   4       // argmax-key shards

#define LOGITS_ELEMS 132096
#define HC_ELEMS     16384

// smem floats: sW 8192 | sh 20480 | sred 128 | sE(8) | sOH 2112
#define OH_STRIDE 132
#define SMEM_FLOATS (8192 + 20480 + 128 + 8 + 16 * OH_STRIDE)
#define SMEM_BYTES  (SMEM_FLOATS * 4)

__device__ __align__(16) float g_pre[TT * 2048 * BB];   // [t][row][b]
__device__ __align__(16) float g_h[HID * BB];           // h, PAIR-PACKED [kp][b][2]
__device__ __align__(16) float g_th[HID * BB];          // tanh(h), [k][b]
__device__ __align__(16) unsigned long long g_best2[TT][BSH][BB];  // sharded argmax keys
__device__ __align__(128) unsigned g_hdone2[TT * NSH * 32];  // +8 per launch per shard
__device__ __align__(128) unsigned g_done2[TT * NSH * 32];   // +8 (+1 shard0) per launch
__device__ __align__(128) unsigned g_epoch;                  // +1 per launch

__device__ __forceinline__ float sigm(float x) { return 1.f / (1.f + __expf(-x)); }
__device__ __forceinline__ float tanh_p(float x) {
    float e = __expf(-2.f * fabsf(x));
    float r = (1.f - e) / (1.f + e);
    return copysignf(r, x);
}
__device__ __forceinline__ void ffma2u(unsigned long long& acc, unsigned long long w, unsigned long long h) {
    asm volatile("fma.rn.f32x2 %0, %1, %2, %0;" : "+l"(acc) : "l"(w), "l"(h));
}
__device__ __forceinline__ float2 unpack2(unsigned long long v) {
    float2 r; asm("mov.b64 {%0, %1}, %2;" : "=f"(r.x), "=f"(r.y) : "l"(v)); return r;
}
__device__ __forceinline__ unsigned long long pack_key(float f, int o) {
    unsigned u = __float_as_uint(f);
    u = (u & 0x80000000u) ? ~u : (u | 0x80000000u);
    return (((unsigned long long)u) << 32) | (unsigned)(255 - o);
}
// red.release orders ALL prior writes of this thread AND (via the preceding
// __syncthreads happens-before edge) of the whole CTA — no MEMBAR needed.
__device__ __forceinline__ void rel_add(unsigned* p) {
    asm volatile("red.release.gpu.global.add.u32 [%0], 1;" :: "l"(p) : "memory");
}
__device__ __forceinline__ void acq_poll(const unsigned* p, unsigned want) {
    unsigned v;
    do {
        asm volatile("ld.acquire.gpu.global.u32 %0, [%1];" : "=r"(v) : "l"(p) : "memory");
    } while ((int)(v - want) < 0);
}
__device__ __forceinline__ unsigned long long ldcg_u64(const unsigned long long* p) {
    unsigned long long v;
    asm volatile("ld.global.cg.u64 %0, [%1];" : "=l"(v) : "l"(p) : "memory");
    return v;
}

__global__ void __launch_bounds__(NTHR, 1)
decoder_kernel(const float* __restrict__ chords, const float* __restrict__ latent,
               const float* __restrict__ W_ih, const float* __restrict__ W_hh,
               const float* __restrict__ b_ih, const float* __restrict__ b_hh,
               const float* __restrict__ W_lin, const float* __restrict__ b_lin,
               float* __restrict__ out, int out_size)
{
    extern __shared__ float smem[];
    float* sW   = smem;                       // 8192
    float* sh   = smem + 8192;                // 20480
    float* sred = smem + 8192 + 20480;        // 128
    unsigned* sE = (unsigned*)(sred + 128);   // 8
    float* sOH  = sred + 128 + 8;             // 16*132: one-hot W_ih block [u*4+g][o]

    const int tid  = threadIdx.x;
    const int lane = tid & 31;
    const int wid  = tid >> 5;
    const int bid  = blockIdx.x;         // 0..128; bid==128 is logits-only
    const int j    = (bid << 2) + wid;   // hidden unit (valid for bid < 128)

    if (tid == 0) {
        unsigned e0;
        asm volatile("ld.acquire.gpu.global.u32 %0, [%1];"
                     : "=r"(e0) : "l"(&g_epoch) : "memory");
        sE[0] = e0;
    }
    // per-launch reset of sharded argmax keys (CTA bid<32 owns slot t=bid);
    // visible to red.max writers via their hdone[t] acquire (this CTA's step-t
    // release is ordered after these plain stores).
    if (bid < TT) ((unsigned long long*)g_best2[bid])[tid] = 0ull;   // 128 = BSH*BB

    if (bid < NGATE) {
        // ---- Stage W_hh rows into smem ----
        {
            float* dst = sW + wid * 2048;
            #pragma unroll
            for (int g = 0; g < 4; ++g) {
                const float* src = W_hh + (size_t)(g * HID + j) * HID;
                for (int k = (lane << 2); k < 512; k += 128)
                    *(float4*)(dst + g * 512 + k) = *(const float4*)(src + k);
            }
        }
        // ---- Stage W_ih one-hot block: rows {g*512 + (bid*4+u)}, cols 256..384 ----
        for (int i = tid; i < 16 * NOUT; i += NTHR) {
            const int r   = i / NOUT;       // r = u*4+g
            const int o   = i - r * NOUT;
            const int u   = r >> 2, g = r & 3;
            const int row = g * HID + (bid << 2) + u;
            sOH[r * OH_STRIDE + o] = __ldg(W_ih + (size_t)row * INF_ + 256 + o);
        }
        for (int i = tid; i < BB * 256; i += NTHR) {
            int b = i >> 8, l = i & 255;
            sh[l * 32 + b] = latent[i];
        }
        {
            float* sch = sh + 8192;
            for (int i = tid; i < BB * TT * 12; i += NTHR) {
                int b = i / 384, rem = i - b * 384;
                sch[rem * 32 + b] = chords[i];
            }
        }
        __syncthreads();
        // ---- Precompute g_pre[t][row][b] ----
        {
            const float* sch = sh + 8192;
            #pragma unroll
            for (int g = 0; g < 4; ++g) {
                const int row = g * HID + j;
                const float* wrow = W_ih + (size_t)row * INF_;
                float acc = __ldg(b_ih + row) + __ldg(b_hh + row);
                #pragma unroll 8
                for (int k = 0; k < 256; ++k)
                    acc = fmaf(sh[k * 32 + lane], __ldg(wrow + k), acc);
                float wc[12];
                #pragma unroll
                for (int cc = 0; cc < 12; ++cc) wc[cc] = __ldg(wrow + 385 + cc);
                for (int t = 0; t < TT; ++t) {
                    float z = acc;
                    #pragma unroll
                    for (int cc = 0; cc < 12; ++cc)
                        z = fmaf(sch[(t * 12 + cc) * 32 + lane], wc[cc], z);
                    g_pre[((size_t)(t * 2048) + row) * 32 + lane] = z;
                }
            }
        }
        __syncthreads();
    } else {
        __syncthreads();
    }
    const unsigned ep0 = sE[0];
    const unsigned HT  = (ep0 + 1) * (NGATE / NSH);
    const unsigned DT  = (ep0 + 1) * (NBLK / NSH);
    const unsigned DT0 = (ep0 + 1) * (NBLK / NSH + 1);

    const int r0 = j, r1 = HID + j, r2 = 2 * HID + j, r3 = 3 * HID + j;
    const float* w0 = sW + wid * 2048;
    const float* w1 = w0 + 512;
    const float* w2 = w0 + 1024;
    const float* w3 = w0 + 1536;
    const float* oh = sOH + wid * 4 * OH_STRIDE;
    const int csh = bid & (NSH - 1);
    const int ksh = bid & (BSH - 1);

    float creg = 0.f;

    for (int t = 0; t < TT; ++t) {
        if (bid < NGATE) {
            __syncthreads();   // sh holds h(t-1); staging STS drained last iteration

            const float* prebase = g_pre + (size_t)(t * 2048) * 32;
            float zi = prebase[r0 * 32 + lane];
            float zf = prebase[r1 * 32 + lane];
            float zg = prebase[r2 * 32 + lane];
            float zo = prebase[r3 * 32 + lane];

            if (t > 0) {
                // ---- recurrent dot FIRST (doesn't need pidx) ----
                const unsigned long long* sh64 = (const unsigned long long*)sh;
                unsigned long long A0 = 0, A1 = 0, A2 = 0, A3 = 0;
                #pragma unroll 4
                for (int k = 0; k < 512; k += 4) {
                    const int kp = k >> 1;
                    unsigned long long h01 = sh64[kp * 32 + lane];
                    unsigned long long h23 = sh64[(kp + 1) * 32 + lane];
                    ulonglong2 Wa = *(const ulonglong2*)(w0 + k);
                    ulonglong2 Wb = *(const ulonglong2*)(w1 + k);
                    ulonglong2 Wc = *(const ulonglong2*)(w2 + k);
                    ulonglong2 Wd = *(const ulonglong2*)(w3 + k);
                    ffma2u(A0, Wa.x, h01); ffma2u(A1, Wb.x, h01);
                    ffma2u(A2, Wc.x, h01); ffma2u(A3, Wd.x, h01);
                    ffma2u(A0, Wa.y, h23); ffma2u(A1, Wb.y, h23);
                    ffma2u(A2, Wc.y, h23); ffma2u(A3, Wd.y, h23);
                }

                // ---- wait for argmax(t-1) (also certifies gen-(t-1) reads done)
                if (tid < NSH)
                    acq_poll(&g_done2[((t - 1) * NSH + tid) * 32], tid == 0 ? DT0 : DT);
                __syncthreads();
                unsigned long long key = ldcg_u64(&g_best2[t - 1][0][lane]);
                #pragma unroll
                for (int s = 1; s < BSH; ++s) {
                    unsigned long long k2 = ldcg_u64(&g_best2[t - 1][s][lane]);
                    if (k2 > key) key = k2;
                }
                const int pidx = 255 - (int)(unsigned)(key & 0xffu);

                // one-hot gather from SMEM (same float values as the old __ldg)
                zi += oh[0 * OH_STRIDE + pidx];
                zf += oh[1 * OH_STRIDE + pidx];
                zg += oh[2 * OH_STRIDE + pidx];
                zo += oh[3 * OH_STRIDE + pidx];
                float2 u0 = unpack2(A0), u1 = unpack2(A1);
                float2 u2 = unpack2(A2), u3 = unpack2(A3);
                zi += u0.x + u0.y; zf += u1.x + u1.y;
                zg += u2.x + u2.y; zo += u3.x + u3.y;
            }

            const float gi = sigm(zi), gf = sigm(zf), gg = tanh_p(zg), go = sigm(zo);
            creg = gf * creg + gi * gg;
            const float hv = go * tanh_p(creg);
            const float th = tanh_p(hv);
            g_h[(j >> 1) * 64 + lane * 2 + (j & 1)] = hv;   // pair-packed
            g_th[j * 32 + lane] = th;                       // [k][b]
            if (t == TT - 1 && out_size >= LOGITS_ELEMS + 2 * HC_ELEMS) {
                out[LOGITS_ELEMS + lane * HID + j]            = hv;
                out[LOGITS_ELEMS + HC_ELEMS + lane * HID + j] = creg;
            }
            __syncthreads();            // all 4 warps' h/th stores done
            if (tid == 0) rel_add(&g_hdone2[(t * NSH + csh) * 32]);   // NO MEMBAR
        }

        // ---- wait until ALL gate CTAs published h(t)/th(t) ----
        if (tid < NSH) acq_poll(&g_hdone2[(t * NSH + tid) * 32], HT);
        __syncthreads();

        // ---- stage h(t) for next step's dot (gate CTAs; overlaps logits) ----
        if (bid < NGATE && t < TT - 1) {
            const float4* src4 = (const float4*)g_h;
            float4* dst4 = (float4*)sh;
            #pragma unroll 4
            for (int i = tid; i < HID * BB / 4; i += NTHR) dst4[i] = __ldcg(src4 + i);
        }

        // ---- logits column o = bid (all CTAs; arithmetic identical) ----
        {
            const int o = bid;
            const float* wl  = W_lin + (size_t)o * HID + wid * 128;
            const float* thp = g_th + (wid * 128) * 32;
            float c0 = 0.f, c1 = 0.f, c2 = 0.f, c3 = 0.f;
            #pragma unroll
            for (int k = 0; k < 128; k += 4) {
                c0 = fmaf(__ldcg(thp + (k + 0) * 32 + lane), __ldg(wl + k + 0), c0);
                c1 = fmaf(__ldcg(thp + (k + 1) * 32 + lane), __ldg(wl + k + 1), c1);
                c2 = fmaf(__ldcg(thp + (k + 2) * 32 + lane), __ldg(wl + k + 2), c2);
                c3 = fmaf(__ldcg(thp + (k + 3) * 32 + lane), __ldg(wl + k + 3), c3);
            }
            sred[wid * 32 + lane] = (c0 + c1) + (c2 + c3);
            __syncthreads();   // drains staging STS (h(t) reads retired) + sred
            if (wid == 0) {
                float tot = sred[lane] + sred[32 + lane] + sred[64 + lane]
                          + sred[96 + lane] + __ldg(b_lin + o);
                out[lane * (TT * NOUT) + t * NOUT + o] = tot;
                if (t < TT - 1) {
                    unsigned long long key = pack_key(tot, o);
                    asm volatile("red.relaxed.gpu.global.max.u64 [%0], %1;"
                                 :: "l"(&g_best2[t][ksh][lane]), "l"(key) : "memory");
                }
            }
            __syncthreads();
            if (t < TT - 1 && tid == 0)
                rel_add(&g_done2[(t * NSH + csh) * 32]);   // NO MEMBAR
        }
    }

    if (bid == 0 && tid == 0) rel_add(&g_epoch);
}

extern "C" void kernel_launch(void* const* d_in, const int* in_sizes, int n_in,
                              void* d_out, int out_size) {
    const int want[8] = {12288, 8192, 813056, 1048576, 2048, 2048, 66048, 129};
    const float* p[8] = {nullptr, nullptr, nullptr, nullptr, nullptr, nullptr, nullptr, nullptr};
    bool used[64] = {false};
    for (int w = 0; w < 8; ++w) {
        for (int i = 0; i < n_in && i < 64; ++i) {
            if (!used[i] && in_sizes[i] == want[w]) {
                p[w] = (const float*)d_in[i];
                used[i] = true;
                break;
            }
        }
    }
    cudaFuncSetAttribute(decoder_kernel, cudaFuncAttributeMaxDynamicSharedMemorySize, SMEM_BYTES);
    decoder_kernel<<<NBLK, NTHR, SMEM_BYTES>>>(p[0], p[1], p[2], p[3], p[4], p[5], p[6], p[7],
                                               (float*)d_out, out_size);
}

// round 17
// speedup vs baseline: 2.0134x; 1.2724x over previous
#include <cuda_runtime.h>
#include <cstdint>

#define NGATE 128
#define NBLK  129
#define NTHR  256
#define HID   512
#define BB    32
#define TT    32
#define INF_  397
#define NOUT  129
#define NSH   16      // counter shards (one 128B line each)
#define BSH   4       // argmax-key shards

#define LOGITS_ELEMS 132096
#define HC_ELEMS     16384

// smem floats: sW 8192 | sh 20480 | sred 256 | sE 8 | sOH 16*132 | sComb 1024 (512 u64)
#define OH_STRIDE 132
#define SMEM_FLOATS (8192 + 20480 + 256 + 8 + 16 * OH_STRIDE + 1024)
#define SMEM_BYTES  (SMEM_FLOATS * 4)

__device__ __align__(16) float g_pre[TT * 2048 * BB];   // [t][row][b]
__device__ __align__(16) float g_h[HID * BB];           // h, PAIR-PACKED [kp][b][2]
__device__ __align__(16) float g_th[HID * BB];          // tanh(h), [k][b]
__device__ __align__(16) unsigned long long g_best2[TT][BSH][BB];  // sharded argmax keys
__device__ __align__(128) unsigned g_hdone2[TT * NSH * 32];  // +8 per launch per shard
__device__ __align__(128) unsigned g_done2[TT * NSH * 32];   // +8 (+1 shard0) per launch
__device__ __align__(128) unsigned g_epoch;                  // +1 per launch

__device__ __forceinline__ float sigm(float x) { return 1.f / (1.f + __expf(-x)); }
__device__ __forceinline__ float tanh_p(float x) {
    float e = __expf(-2.f * fabsf(x));
    float r = (1.f - e) / (1.f + e);
    return copysignf(r, x);
}
__device__ __forceinline__ void ffma2u(unsigned long long& acc, unsigned long long w, unsigned long long h) {
    asm volatile("fma.rn.f32x2 %0, %1, %2, %0;" : "+l"(acc) : "l"(w), "l"(h));
}
__device__ __forceinline__ float2 unpack2(unsigned long long v) {
    float2 r; asm("mov.b64 {%0, %1}, %2;" : "=f"(r.x), "=f"(r.y) : "l"(v)); return r;
}
__device__ __forceinline__ unsigned long long pack_key(float f, int o) {
    unsigned u = __float_as_uint(f);
    u = (u & 0x80000000u) ? ~u : (u | 0x80000000u);
    return (((unsigned long long)u) << 32) | (unsigned)(255 - o);
}
__device__ __forceinline__ void rel_add(unsigned* p) {
    asm volatile("red.release.gpu.global.add.u32 [%0], 1;" :: "l"(p) : "memory");
}
__device__ __forceinline__ void acq_poll(const unsigned* p, unsigned want) {
    unsigned v;
    do {
        asm volatile("ld.acquire.gpu.global.u32 %0, [%1];" : "=r"(v) : "l"(p) : "memory");
    } while ((int)(v - want) < 0);
}
__device__ __forceinline__ unsigned long long ldcg_u64(const unsigned long long* p) {
    unsigned long long v;
    asm volatile("ld.global.cg.u64 %0, [%1];" : "=l"(v) : "l"(p) : "memory");
    return v;
}

__global__ void __launch_bounds__(NTHR, 1)
decoder_kernel(const float* __restrict__ chords, const float* __restrict__ latent,
               const float* __restrict__ W_ih, const float* __restrict__ W_hh,
               const float* __restrict__ b_ih, const float* __restrict__ b_hh,
               const float* __restrict__ W_lin, const float* __restrict__ b_lin,
               float* __restrict__ out, int out_size)
{
    extern __shared__ float smem[];
    float* sW   = smem;                       // 8192
    float* sh   = smem + 8192;                // 20480
    float* sred = smem + 8192 + 20480;        // 256
    unsigned* sE = (unsigned*)(sred + 256);   // 8
    float* sOH  = sred + 256 + 8;             // 16*132
    unsigned long long* sComb = (unsigned long long*)(sOH + 16 * OH_STRIDE);  // 512 u64

    const int tid  = threadIdx.x;
    const int lane = tid & 31;
    const int wid  = tid >> 5;           // 0..7
    const int u    = wid & 3;            // unit within CTA
    const int hf   = wid >> 2;           // k-half
    const int bid  = blockIdx.x;         // 0..128; bid==128 is logits-only
    const int j    = (bid << 2) + u;     // hidden unit (valid for bid < 128)

    if (tid == 0) {
        unsigned e0;
        asm volatile("ld.acquire.gpu.global.u32 %0, [%1];"
                     : "=r"(e0) : "l"(&g_epoch) : "memory");
        sE[0] = e0;
    }
    // per-launch reset of sharded argmax keys (CTA bid<32 owns slot t=bid);
    // visible to red.max writers via their hdone[t] acquire.
    if (bid < TT && tid < BSH * BB) ((unsigned long long*)g_best2[bid])[tid] = 0ull;

    if (bid < NGATE) {
        // ---- Stage W_hh: warp (u,hf) loads its k-half of unit u's 4 gate rows ----
        {
            #pragma unroll
            for (int g = 0; g < 4; ++g) {
                const float* src = W_hh + (size_t)(g * HID + j) * HID;
                float* dst = sW + u * 2048 + g * 512;
                for (int k = hf * 256 + (lane << 2); k < hf * 256 + 256; k += 128)
                    *(float4*)(dst + k) = *(const float4*)(src + k);
            }
        }
        // ---- Stage W_ih one-hot block: rows {g*512 + (bid*4+uu)}, cols 256..384 ----
        for (int i = tid; i < 16 * NOUT; i += NTHR) {
            const int r   = i / NOUT;       // r = uu*4+g
            const int o   = i - r * NOUT;
            const int uu  = r >> 2, g = r & 3;
            const int row = g * HID + (bid << 2) + uu;
            sOH[r * OH_STRIDE + o] = __ldg(W_ih + (size_t)row * INF_ + 256 + o);
        }
        for (int i = tid; i < BB * 256; i += NTHR) {
            int b = i >> 8, l = i & 255;
            sh[l * 32 + b] = latent[i];
        }
        {
            float* sch = sh + 8192;
            for (int i = tid; i < BB * TT * 12; i += NTHR) {
                int b = i / 384, rem = i - b * 384;
                sch[rem * 32 + b] = chords[i];
            }
        }
        __syncthreads();
        // ---- Precompute g_pre: warp (u,hf) handles gates g = 2*hf + {0,1} of unit u ----
        {
            const float* sch = sh + 8192;
            #pragma unroll
            for (int gg = 0; gg < 2; ++gg) {
                const int g   = 2 * hf + gg;
                const int row = g * HID + j;
                const float* wrow = W_ih + (size_t)row * INF_;
                float acc = __ldg(b_ih + row) + __ldg(b_hh + row);
                #pragma unroll 8
                for (int k = 0; k < 256; ++k)
                    acc = fmaf(sh[k * 32 + lane], __ldg(wrow + k), acc);
                float wc[12];
                #pragma unroll
                for (int cc = 0; cc < 12; ++cc) wc[cc] = __ldg(wrow + 385 + cc);
                for (int t = 0; t < TT; ++t) {
                    float z = acc;
                    #pragma unroll
                    for (int cc = 0; cc < 12; ++cc)
                        z = fmaf(sch[(t * 12 + cc) * 32 + lane], wc[cc], z);
                    g_pre[((size_t)(t * 2048) + row) * 32 + lane] = z;
                }
            }
        }
        __syncthreads();
    } else {
        __syncthreads();
    }
    const unsigned ep0 = sE[0];
    const unsigned HT  = (ep0 + 1) * (NGATE / NSH);
    const unsigned DT  = (ep0 + 1) * (NBLK / NSH);
    const unsigned DT0 = (ep0 + 1) * (NBLK / NSH + 1);

    const int r0 = j, r1 = HID + j, r2 = 2 * HID + j, r3 = 3 * HID + j;
    const float* w0 = sW + u * 2048;
    const float* w1 = w0 + 512;
    const float* w2 = w0 + 1024;
    const float* w3 = w0 + 1536;
    const float* oh = sOH + u * 4 * OH_STRIDE;
    const int kp0 = hf * 128;            // pair-index start of this warp's k-half
    const int csh = bid & (NSH - 1);
    const int ksh = bid & (BSH - 1);

    float creg = 0.f;

    for (int t = 0; t < TT; ++t) {
        if (bid < NGATE) {
            __syncthreads();   // sh holds h(t-1); staging STS drained last iteration

            float zi = 0.f, zf = 0.f, zg = 0.f, zo = 0.f;
            if (hf == 0) {
                const float* prebase = g_pre + (size_t)(t * 2048) * 32;
                zi = prebase[r0 * 32 + lane];
                zf = prebase[r1 * 32 + lane];
                zg = prebase[r2 * 32 + lane];
                zo = prebase[r3 * 32 + lane];
            }

            if (t > 0) {
                // ---- k-split recurrent dot: this warp covers k in [hf*256, hf*256+256)
                const unsigned long long* sh64 = (const unsigned long long*)sh;
                unsigned long long A0 = 0, A1 = 0, A2 = 0, A3 = 0;
                #pragma unroll 4
                for (int kp = kp0; kp < kp0 + 128; kp += 2) {
                    unsigned long long h01 = sh64[kp * 32 + lane];
                    unsigned long long h23 = sh64[(kp + 1) * 32 + lane];
                    const int k = kp * 2;
                    ulonglong2 Wa = *(const ulonglong2*)(w0 + k);
                    ulonglong2 Wb = *(const ulonglong2*)(w1 + k);
                    ulonglong2 Wc = *(const ulonglong2*)(w2 + k);
                    ulonglong2 Wd = *(const ulonglong2*)(w3 + k);
                    ffma2u(A0, Wa.x, h01); ffma2u(A1, Wb.x, h01);
                    ffma2u(A2, Wc.x, h01); ffma2u(A3, Wd.x, h01);
                    ffma2u(A0, Wa.y, h23); ffma2u(A1, Wb.y, h23);
                    ffma2u(A2, Wc.y, h23); ffma2u(A3, Wd.y, h23);
                }
                if (hf == 1) {
                    sComb[(u * 4 + 0) * 32 + lane] = A0;
                    sComb[(u * 4 + 1) * 32 + lane] = A1;
                    sComb[(u * 4 + 2) * 32 + lane] = A2;
                    sComb[(u * 4 + 3) * 32 + lane] = A3;
                }

                // ---- wait for argmax(t-1) (also certifies gen-(t-1) reads done)
                if (tid < NSH)
                    acq_poll(&g_done2[((t - 1) * NSH + tid) * 32], tid == 0 ? DT0 : DT);
                __syncthreads();   // orders sComb writes + poll

                if (hf == 0) {
                    unsigned long long key = ldcg_u64(&g_best2[t - 1][0][lane]);
                    #pragma unroll
                    for (int s = 1; s < BSH; ++s) {
                        unsigned long long k2 = ldcg_u64(&g_best2[t - 1][s][lane]);
                        if (k2 > key) key = k2;
                    }
                    const int pidx = 255 - (int)(unsigned)(key & 0xffu);

                    zi += oh[0 * OH_STRIDE + pidx];
                    zf += oh[1 * OH_STRIDE + pidx];
                    zg += oh[2 * OH_STRIDE + pidx];
                    zo += oh[3 * OH_STRIDE + pidx];
                    float2 p0 = unpack2(A0), q0 = unpack2(sComb[(u * 4 + 0) * 32 + lane]);
                    float2 p1 = unpack2(A1), q1 = unpack2(sComb[(u * 4 + 1) * 32 + lane]);
                    float2 p2 = unpack2(A2), q2 = unpack2(sComb[(u * 4 + 2) * 32 + lane]);
                    float2 p3 = unpack2(A3), q3 = unpack2(sComb[(u * 4 + 3) * 32 + lane]);
                    zi += p0.x + p0.y + q0.x + q0.y;
                    zf += p1.x + p1.y + q1.x + q1.y;
                    zg += p2.x + p2.y + q2.x + q2.y;
                    zo += p3.x + p3.y + q3.x + q3.y;
                }
            }

            if (hf == 0) {
                const float gi = sigm(zi), gf = sigm(zf), gg = tanh_p(zg), go = sigm(zo);
                creg = gf * creg + gi * gg;
                const float hv = go * tanh_p(creg);
                const float th = tanh_p(hv);
                g_h[(j >> 1) * 64 + lane * 2 + (j & 1)] = hv;   // pair-packed
                g_th[j * 32 + lane] = th;                       // [k][b]
                if (t == TT - 1 && out_size >= LOGITS_ELEMS + 2 * HC_ELEMS) {
                    out[LOGITS_ELEMS + lane * HID + j]            = hv;
                    out[LOGITS_ELEMS + HC_ELEMS + lane * HID + j] = creg;
                }
            }
            __syncthreads();            // h/th stores done CTA-wide
            if (tid == 0) rel_add(&g_hdone2[(t * NSH + csh) * 32]);
        }

        // ---- wait until ALL gate CTAs published h(t)/th(t) ----
        if (tid < NSH) acq_poll(&g_hdone2[(t * NSH + tid) * 32], HT);
        __syncthreads();

        // ---- stage h(t) for next step's dot (gate CTAs; 16 float4/thread) ----
        if (bid < NGATE && t < TT - 1) {
            const float4* src4 = (const float4*)g_h;
            float4* dst4 = (float4*)sh;
            #pragma unroll 4
            for (int i = tid; i < HID * BB / 4; i += NTHR) dst4[i] = __ldcg(src4 + i);
        }

        // ---- logits column o = bid: 8 warps x 64-k segments ----
        {
            const int o = bid;
            const float* wl  = W_lin + (size_t)o * HID + wid * 64;
            const float* thp = g_th + (wid * 64) * 32;
            float c0 = 0.f, c1 = 0.f, c2 = 0.f, c3 = 0.f;
            #pragma unroll
            for (int k = 0; k < 64; k += 4) {
                c0 = fmaf(__ldcg(thp + (k + 0) * 32 + lane), __ldg(wl + k + 0), c0);
                c1 = fmaf(__ldcg(thp + (k + 1) * 32 + lane), __ldg(wl + k + 1), c1);
                c2 = fmaf(__ldcg(thp + (k + 2) * 32 + lane), __ldg(wl + k + 2), c2);
                c3 = fmaf(__ldcg(thp + (k + 3) * 32 + lane), __ldg(wl + k + 3), c3);
            }
            sred[wid * 32 + lane] = (c0 + c1) + (c2 + c3);
            __syncthreads();   // drains staging STS + sred
            if (wid == 0) {
                float tot = ((sred[lane] + sred[32 + lane]) + (sred[64 + lane] + sred[96 + lane]))
                          + ((sred[128 + lane] + sred[160 + lane]) + (sred[192 + lane] + sred[224 + lane]))
                          + __ldg(b_lin + o);
                out[lane * (TT * NOUT) + t * NOUT + o] = tot;
                if (t < TT - 1) {
                    unsigned long long key = pack_key(tot, o);
                    asm volatile("red.relaxed.gpu.global.max.u64 [%0], %1;"
                                 :: "l"(&g_best2[t][ksh][lane]), "l"(key) : "memory");
                }
            }
            __syncthreads();
            if (t < TT - 1 && tid == 0)
                rel_add(&g_done2[(t * NSH + csh) * 32]);
        }
    }

    if (bid == 0 && tid == 0) rel_add(&g_epoch);
}

extern "C" void kernel_launch(void* const* d_in, const int* in_sizes, int n_in,
                              void* d_out, int out_size) {
    const int want[8] = {12288, 8192, 813056, 1048576, 2048, 2048, 66048, 129};
    const float* p[8] = {nullptr, nullptr, nullptr, nullptr, nullptr, nullptr, nullptr, nullptr};
    bool used[64] = {false};
    for (int w = 0; w < 8; ++w) {
        for (int i = 0; i < n_in && i < 64; ++i) {
            if (!used[i] && in_sizes[i] == want[w]) {
                p[w] = (const float*)d_in[i];
                used[i] = true;
                break;
            }
        }
    }
    cudaFuncSetAttribute(decoder_kernel, cudaFuncAttributeMaxDynamicSharedMemorySize, SMEM_BYTES);
    decoder_kernel<<<NBLK, NTHR, SMEM_BYTES>>>(p[0], p[1], p[2], p[3], p[4], p[5], p[6], p[7],
                                               (float*)d_out, out_size);
}